// round 13
// baseline (speedup 1.0000x reference)
#include <cuda_runtime.h>
#include <cstdint>

// Problem constants (match reference)
static constexpr int B_ = 4096;   // batch
static constexpr int D_ = 512;    // theta dim
static constexpr int K_ = 128;    // mixture comps
static constexpr int A_ = 32;     // alpha dim
static constexpr int P_ = 16;     // hutchinson probes
static constexpr int DT_ = D_ / 64; // d-tiles in wm_loss (8)

// Scratch (device globals; no allocation allowed)
__device__ float g_mu[K_ * D_];        // mu[k][d]
__device__ float g_muT[D_ * K_];       // mu^T[d][k]
__device__ __align__(16) char g_q[K_ * D_ * 2];  // interleaved (hi,lo) int8: 64*hi+lo = round(mu*1024)
__device__ float g_musq[K_];           // ||mu_k||^2
__device__ float g_S[B_ * K_];         // softmax weights
__device__ float g_traceP[P_][B_];     // per-probe  sum_k w y^2 - (sum_k w y)^2
__device__ float g_lossPart[DT_][B_];  // per-d-tile sum_d (m - theta)^2
__device__ double g_part[16];          // final partial sums

// ================= portable PTX helpers =================
__device__ __forceinline__ uint32_t smem_u32(const void* p) {
    uint32_t a;
    asm("{ .reg .u64 t; cvta.to.shared.u64 t, %1; cvt.u32.u64 %0, t; }"
        : "=r"(a) : "l"(p));
    return a;
}
__device__ __forceinline__ void ldsm_x4(uint32_t& r0, uint32_t& r1, uint32_t& r2,
                                        uint32_t& r3, uint32_t addr) {
    asm volatile("ldmatrix.sync.aligned.m8n8.x4.shared.b16 {%0,%1,%2,%3}, [%4];"
                 : "=r"(r0), "=r"(r1), "=r"(r2), "=r"(r3) : "r"(addr));
}
__device__ __forceinline__ void ldsm_x2(uint32_t& r0, uint32_t& r1, uint32_t addr) {
    asm volatile("ldmatrix.sync.aligned.m8n8.x2.shared.b16 {%0,%1}, [%2];"
                 : "=r"(r0), "=r"(r1) : "r"(addr));
}
__device__ __forceinline__ void imma_s8(int* c, uint32_t a0, uint32_t a1,
                                        uint32_t a2, uint32_t a3,
                                        uint32_t b0, uint32_t b1) {
    asm volatile(
        "mma.sync.aligned.m16n8k32.row.col.s32.s8.s8.s32 "
        "{%0,%1,%2,%3}, {%4,%5,%6,%7}, {%8,%9}, {%0,%1,%2,%3};"
        : "+r"(c[0]), "+r"(c[1]), "+r"(c[2]), "+r"(c[3])
        : "r"(a0), "r"(a1), "r"(a2), "r"(a3), "r"(b0), "r"(b1));
}
// 64B-row swizzle
__device__ __forceinline__ uint32_t sw64(uint32_t o) { return o ^ ((o >> 3) & 0x30u); }

// pack two Rademacher ints (0/1) into int8 pairs (+-64, +-1) per 16-bit lane:
// v=1 -> (64, 1) = 0x0140 ; v=0 -> (-64, -1) = 0xFFC0
__device__ __forceinline__ uint32_t pk2(int v0, int v1) {
    return (v0 ? 0x0140u : 0xFFC0u) | (v1 ? 0x01400000u : 0xFFC00000u);
}

// ---------------- packed f32x2 helpers (FFMA2 path, logits GEMM) -------------
__device__ __forceinline__ unsigned long long ffma2(unsigned long long a,
                                                    unsigned long long b,
                                                    unsigned long long c) {
    unsigned long long d;
    asm("fma.rn.f32x2 %0, %1, %2, %3;" : "=l"(d) : "l"(a), "l"(b), "l"(c));
    return d;
}
__device__ __forceinline__ void unpack2(unsigned long long v, float& lo, float& hi) {
    asm("mov.b64 {%0, %1}, %2;" : "=f"(lo), "=f"(hi) : "l"(v));
}

// ---------------- K1: mu = alpha @ W, mu^T, ||mu_k||^2, int8 hi/lo -----------
__global__ void __launch_bounds__(128) mu_kernel(const float* __restrict__ alpha,
                                                 const float* __restrict__ W) {
    int k = blockIdx.x;
    int t = threadIdx.x;
    __shared__ float as[A_];
    if (t < A_) as[t] = alpha[k * A_ + t];
    __syncthreads();
    float sq = 0.f;
#pragma unroll
    for (int rep = 0; rep < D_ / 128; rep++) {
        int d = rep * 128 + t;
        float acc = 0.f;
#pragma unroll
        for (int a = 0; a < A_; a++) acc = fmaf(as[a], W[a * D_ + d], acc);
        g_mu[k * D_ + d] = acc;
        g_muT[(size_t)d * K_ + k] = acc;
        int q = __float2int_rn(acc * 1024.0f);
        q = max(-8159, min(8159, q));
        int hi = (q + 32) >> 6;          // round-to-nearest 64-split
        int lo = q - (hi << 6);          // in [-32, 31]
        char2 pr; pr.x = (char)hi; pr.y = (char)lo;
        *(char2*)&g_q[((size_t)k * D_ + d) * 2] = pr;
        sq = fmaf(acc, acc, sq);
    }
    __shared__ float red[4];
#pragma unroll
    for (int off = 16; off; off >>= 1) sq += __shfl_xor_sync(0xffffffffu, sq, off);
    if ((t & 31) == 0) red[t >> 5] = sq;
    __syncthreads();
    if (t == 0) g_musq[k] = red[0] + red[1] + red[2] + red[3];
}

// ---------------- K2: theta @ mu^T + fused row softmax -> g_S ----------------
// BM=64, BN=128(=K), BK=32, 256 threads, 4x8 per thread via f32x2 (R9-proven)
__global__ void __launch_bounds__(256)
logits_softmax_kernel(const float* __restrict__ X) {
    __shared__ float2 As2[64][37];
    __shared__ float  Bs[32][128];
    __shared__ float  musq_s[K_];

    const int rowbase = blockIdx.x * 64;
    const int tid = threadIdx.x;
    const int tx = tid & 15;
    const int ty = tid >> 4;
    if (tid < K_) musq_s[tid] = g_musq[tid];

    unsigned long long acc[4][4];
#pragma unroll
    for (int i = 0; i < 4; i++)
#pragma unroll
        for (int j = 0; j < 4; j++) acc[i][j] = 0ull;

    for (int d0 = 0; d0 < D_; d0 += 32) {
#pragma unroll
        for (int it = 0; it < 2; it++) {
            int idx = tid + it * 256;
            int r = idx >> 3;
            int c4 = (idx & 7) << 2;
            float4 va = *(const float4*)(X + (size_t)(rowbase + r) * D_ + d0 + c4);
            As2[r][c4 + 0] = make_float2(va.x, va.x);
            As2[r][c4 + 1] = make_float2(va.y, va.y);
            As2[r][c4 + 2] = make_float2(va.z, va.z);
            As2[r][c4 + 3] = make_float2(va.w, va.w);
        }
#pragma unroll
        for (int it = 0; it < 4; it++) {
            int idx = tid + it * 256;
            int kk = idx >> 5;
            int n4 = (idx & 31) << 2;
            *(float4*)&Bs[kk][n4] = *(const float4*)(g_muT + (size_t)(d0 + kk) * K_ + n4);
        }
        __syncthreads();
#pragma unroll 8
        for (int kk = 0; kk < 32; kk++) {
            ulonglong2 b01 = *(const ulonglong2*)&Bs[kk][tx * 8];
            ulonglong2 b23 = *(const ulonglong2*)&Bs[kk][tx * 8 + 4];
#pragma unroll
            for (int i = 0; i < 4; i++) {
                unsigned long long aa = *(const unsigned long long*)&As2[ty * 4 + i][kk];
                acc[i][0] = ffma2(aa, b01.x, acc[i][0]);
                acc[i][1] = ffma2(aa, b01.y, acc[i][1]);
                acc[i][2] = ffma2(aa, b23.x, acc[i][2]);
                acc[i][3] = ffma2(aa, b23.y, acc[i][3]);
            }
        }
        __syncthreads();
    }

    // Fused softmax: each row's 128 logits live in the 16-lane tx group.
#pragma unroll
    for (int i = 0; i < 4; i++) {
        int row = rowbase + ty * 4 + i;
        float l[8];
#pragma unroll
        for (int j = 0; j < 4; j++) unpack2(acc[i][j], l[2 * j], l[2 * j + 1]);
#pragma unroll
        for (int j = 0; j < 8; j++) l[j] -= 0.5f * musq_s[tx * 8 + j];
        float m = l[0];
#pragma unroll
        for (int j = 1; j < 8; j++) m = fmaxf(m, l[j]);
#pragma unroll
        for (int off = 8; off; off >>= 1) m = fmaxf(m, __shfl_xor_sync(0xffffffffu, m, off));
        float e[8], s = 0.f;
#pragma unroll
        for (int j = 0; j < 8; j++) { e[j] = expf(l[j] - m); s += e[j]; }
#pragma unroll
        for (int off = 8; off; off >>= 1) s += __shfl_xor_sync(0xffffffffu, s, off);
        float inv = 1.0f / s;
        float4 w0 = make_float4(e[0] * inv, e[1] * inv, e[2] * inv, e[3] * inv);
        float4 w1 = make_float4(e[4] * inv, e[5] * inv, e[6] * inv, e[7] * inv);
        *(float4*)&g_S[(size_t)row * K_ + tx * 8 + 0] = w0;
        *(float4*)&g_S[(size_t)row * K_ + tx * 8 + 4] = w1;
    }
}

// ---------------- K3: probe trace via int8 IMMA (interleaved hi/lo) ----------
// R9-proven pipeline (single buffer, register-staged A prefetch, plain LDG B)
// with IMMA math: A[r, 2d+{0,1}] = (+-64, +-1), B[n, 2d+{0,1}] = (hi, lo)
// -> acc = sum_d +-(64*hi+lo) = 1024*y exactly in int32.
static constexpr int BKD = 32;                // d per chunk (64 int8 k)
static constexpr int NCHI = D_ / BKD;         // 16
static constexpr int TILEB = 128 * 64;        // 8 KB per int8 tile

__global__ void __launch_bounds__(256)
probe_imma_kernel(const int* __restrict__ Vint) {
    __shared__ __align__(1024) char smA[TILEB];
    __shared__ __align__(1024) char smB[TILEB];
    __shared__ float red1[128], red2[128];

    const int tid = threadIdx.x, wid = tid >> 5, lane = tid & 31;
    const int wm = wid & 3, wn = wid >> 2;
    const int g = lane >> 2, tig = lane & 3;
    const int p = blockIdx.y, rowbase = blockIdx.x * 128;
    const size_t vbase = (size_t)p * B_ * D_ + (size_t)rowbase * D_;

    const uint32_t aB = smem_u32(smA);
    const uint32_t bB = smem_u32(smB);

    // Fill indexing: u = tid + i*256: r = u>>2 (0..127), g16 = u&3 (16B unit)
    const int fr0 = tid >> 2, fg0 = tid & 3;
    const int fr1 = (tid + 256) >> 2, fg1 = (tid + 256) & 3;

    int acc[2][8][4];
#pragma unroll
    for (int i = 0; i < 2; i++)
#pragma unroll
        for (int j = 0; j < 8; j++)
#pragma unroll
            for (int q = 0; q < 4; q++) acc[i][j][q] = 0;

    // ldmatrix lane address offsets (verified correct in R12, rel_err 9.7e-7)
    const uint32_t aOff0 = (uint32_t)((wm * 32 + ((lane >> 3) & 1) * 8 + (lane & 7)) * 64 +
                                      (lane >> 4) * 16);
    const uint32_t bOffL = (uint32_t)((wn * 64 + (lane & 7)) * 64 + ((lane >> 3) & 1) * 16);

    // Prologue: stage A ints for chunk 0
    int4 R2[4];
#pragma unroll
    for (int i = 0; i < 2; i++) {
        int r = i ? fr1 : fr0, g16 = i ? fg1 : fg0;
        const int* src = Vint + vbase + (size_t)r * D_ + g16 * 8;
        R2[2 * i] = *(const int4*)(src);
        R2[2 * i + 1] = *(const int4*)(src + 4);
    }

    for (int ch = 0; ch < NCHI; ch++) {
        __syncthreads();   // previous chunk's MMA done before overwriting tiles
        // B tile: plain LDG uint4 (L2-resident) + swizzled STS
#pragma unroll
        for (int i = 0; i < 2; i++) {
            int n = i ? fr1 : fr0, c16 = i ? fg1 : fg0;
            uint4 vb = *(const uint4*)(g_q + (size_t)n * (D_ * 2) + ch * 64 + c16 * 16);
            *(uint4*)(smB + sw64((uint32_t)(n * 64 + c16 * 16))) = vb;
        }
        // A tile: convert staged ints -> packed (+-64, +-1) int8 pairs
#pragma unroll
        for (int i = 0; i < 2; i++) {
            int r = i ? fr1 : fr0, g16 = i ? fg1 : fg0;
            uint4 w;
            w.x = pk2(R2[2 * i].x, R2[2 * i].y);
            w.y = pk2(R2[2 * i].z, R2[2 * i].w);
            w.z = pk2(R2[2 * i + 1].x, R2[2 * i + 1].y);
            w.w = pk2(R2[2 * i + 1].z, R2[2 * i + 1].w);
            *(uint4*)(smA + sw64((uint32_t)(r * 64 + g16 * 16))) = w;
        }
        // Prefetch next chunk's A ints (DRAM latency hides under MMA stage)
        if (ch + 1 < NCHI) {
#pragma unroll
            for (int i = 0; i < 2; i++) {
                int r = i ? fr1 : fr0, g16 = i ? fg1 : fg0;
                const int* src = Vint + vbase + (size_t)r * D_ + (ch + 1) * BKD + g16 * 8;
                R2[2 * i] = *(const int4*)(src);
                R2[2 * i + 1] = *(const int4*)(src + 4);
            }
        }
        __syncthreads();
        // MMA stage: 2 k-steps of 32 int8
#pragma unroll
        for (int ks = 0; ks < 2; ks++) {
            uint32_t a0[4], a1[4];
            ldsm_x4(a0[0], a0[1], a0[2], a0[3], aB + sw64(aOff0 + ks * 32));
            ldsm_x4(a1[0], a1[1], a1[2], a1[3], aB + sw64(aOff0 + 16 * 64 + ks * 32));
#pragma unroll
            for (int nf = 0; nf < 8; nf++) {
                uint32_t b0, b1;
                ldsm_x2(b0, b1, bB + sw64(bOffL + (uint32_t)(nf * 8 * 64) + ks * 32));
                imma_s8(acc[0][nf], a0[0], a0[1], a0[2], a0[3], b0, b1);
                imma_s8(acc[1][nf], a1[0], a1[1], a1[2], a1[3], b0, b1);
            }
        }
    }

    // Epilogue: s1 = sum_k w y^2, s2 = sum_k w y with y = acc/1024
    const float inv1024 = 1.0f / 1024.0f;
    float s1[2][2] = {{0.f, 0.f}, {0.f, 0.f}};
    float s2[2][2] = {{0.f, 0.f}, {0.f, 0.f}};
#pragma unroll
    for (int mf = 0; mf < 2; mf++) {
        int r0 = rowbase + wm * 32 + mf * 16 + g;
#pragma unroll
        for (int nf = 0; nf < 8; nf++) {
            int col = wn * 64 + nf * 8 + tig * 2;
            float2 w0 = __ldg((const float2*)&g_S[(size_t)r0 * K_ + col]);
            float2 w1 = __ldg((const float2*)&g_S[(size_t)(r0 + 8) * K_ + col]);
            float c0 = (float)acc[mf][nf][0] * inv1024;
            float c1 = (float)acc[mf][nf][1] * inv1024;
            float c2 = (float)acc[mf][nf][2] * inv1024;
            float c3 = (float)acc[mf][nf][3] * inv1024;
            s1[mf][0] = fmaf(w0.x * c0, c0, fmaf(w0.y * c1, c1, s1[mf][0]));
            s2[mf][0] = fmaf(w0.x, c0, fmaf(w0.y, c1, s2[mf][0]));
            s1[mf][1] = fmaf(w1.x * c2, c2, fmaf(w1.y * c3, c3, s1[mf][1]));
            s2[mf][1] = fmaf(w1.x, c2, fmaf(w1.y, c3, s2[mf][1]));
        }
    }
#pragma unroll
    for (int mf = 0; mf < 2; mf++)
#pragma unroll
        for (int h = 0; h < 2; h++)
#pragma unroll
            for (int off = 1; off < 4; off <<= 1) {
                s1[mf][h] += __shfl_xor_sync(0xffffffffu, s1[mf][h], off);
                s2[mf][h] += __shfl_xor_sync(0xffffffffu, s2[mf][h], off);
            }
    __syncthreads();
    if (wn == 1 && tig == 0) {
#pragma unroll
        for (int mf = 0; mf < 2; mf++)
#pragma unroll
            for (int h = 0; h < 2; h++) {
                int rl = wm * 32 + mf * 16 + h * 8 + g;
                red1[rl] = s1[mf][h];
                red2[rl] = s2[mf][h];
            }
    }
    __syncthreads();
    if (wn == 0 && tig == 0) {
#pragma unroll
        for (int mf = 0; mf < 2; mf++)
#pragma unroll
            for (int h = 0; h < 2; h++) {
                int rl = wm * 32 + mf * 16 + h * 8 + g;
                float t1 = s1[mf][h] + red1[rl];
                float t2 = s2[mf][h] + red2[rl];
                g_traceP[p][rowbase + rl] = t1 - t2 * t2;
            }
    }
}

// ---------------- K4: M = w @ mu, fused sum_d (m - theta)^2 (R9-proven) ------
__global__ void __launch_bounds__(256)
wm_loss_kernel(const float* __restrict__ theta) {
    __shared__ float Ws[64][36];
    __shared__ float Ms[32][68];

    const int rowbase = blockIdx.x * 64;
    const int d0 = blockIdx.y * 64;
    const int tid = threadIdx.x;
    const int tx = tid & 15;
    const int ty = tid >> 4;

    float acc[4][4];
#pragma unroll
    for (int i = 0; i < 4; i++)
#pragma unroll
        for (int j = 0; j < 4; j++) acc[i][j] = 0.f;

    for (int k0 = 0; k0 < K_; k0 += 32) {
#pragma unroll
        for (int it = 0; it < 2; it++) {
            int idx = tid + it * 256;
            int r = idx >> 3;
            int c4 = (idx & 7) << 2;
            *(float4*)&Ws[r][c4] = *(const float4*)&g_S[(size_t)(rowbase + r) * K_ + k0 + c4];
        }
#pragma unroll
        for (int it = 0; it < 2; it++) {
            int idx = tid + it * 256;
            int kk = idx >> 4;
            int c4 = (idx & 15) << 2;
            *(float4*)&Ms[kk][c4] = *(const float4*)&g_mu[(size_t)(k0 + kk) * D_ + d0 + c4];
        }
        __syncthreads();
#pragma unroll 8
        for (int kk = 0; kk < 32; kk++) {
            float a[4], bb[4];
#pragma unroll
            for (int i = 0; i < 4; i++) a[i] = Ws[ty * 4 + i][kk];
#pragma unroll
            for (int j = 0; j < 4; j++) bb[j] = Ms[kk][tx * 4 + j];
#pragma unroll
            for (int i = 0; i < 4; i++)
#pragma unroll
                for (int j = 0; j < 4; j++) acc[i][j] = fmaf(a[i], bb[j], acc[i][j]);
        }
        __syncthreads();
    }

#pragma unroll
    for (int i = 0; i < 4; i++) {
        int row = rowbase + ty * 4 + i;
        float s = 0.f;
#pragma unroll
        for (int j = 0; j < 4; j++) {
            float th = theta[(size_t)row * D_ + d0 + tx * 4 + j];
            float df = acc[i][j] - th;
            s = fmaf(df, df, s);
        }
#pragma unroll
        for (int off = 8; off; off >>= 1) s += __shfl_xor_sync(0xffffffffu, s, off);
        if (tx == 0) g_lossPart[blockIdx.y][row] = s;
    }
}

// ---------------- K5/K6: two-stage final reduction ---------------------------
__global__ void __launch_bounds__(256)
final_partial(const int* __restrict__ pN) {
    int b = blockIdx.x * 256 + threadIdx.x;
    float Nf = (float)pN[0];
    float temper = Nf / (Nf + 1.0f);
    float tr = 0.f;
#pragma unroll
    for (int p = 0; p < P_; p++) tr += g_traceP[p][b];
    float ls = 0.f;
#pragma unroll
    for (int dt = 0; dt < DT_; dt++) ls += g_lossPart[dt][b];
    double val = (double)(0.5f * temper * temper * ls
                          + temper * (tr * (1.0f / (float)P_) - (float)D_));
    __shared__ double sd[256];
    int t = threadIdx.x;
    sd[t] = val;
    __syncthreads();
    for (int s = 128; s; s >>= 1) {
        if (t < s) sd[t] += sd[t + s];
        __syncthreads();
    }
    if (t == 0) g_part[blockIdx.x] = sd[0];
}

__global__ void final_sum(float* __restrict__ out) {
    if (threadIdx.x == 0) {
        double acc = 0.0;
#pragma unroll
        for (int i = 0; i < 16; i++) acc += g_part[i];
        out[0] = (float)(acc / (double)B_);
    }
}

// ---------------- launch ------------------------------------------------------
extern "C" void kernel_launch(void* const* d_in, const int* in_sizes, int n_in,
                              void* d_out, int out_size) {
    const float* thetas = (const float*)d_in[0];  // [B, D]
    const float* alpha  = (const float*)d_in[1];  // [K, A]
    const float* W      = (const float*)d_in[2];  // [A, D]
    const int*   v_int  = (const int*)d_in[3];    // [P, B, D]
    const int*   pN     = (const int*)d_in[4];    // N_dataset
    float* out = (float*)d_out;

    mu_kernel<<<K_, 128>>>(alpha, W);
    logits_softmax_kernel<<<B_ / 64, 256>>>(thetas);              // logits + softmax
    probe_imma_kernel<<<dim3(B_ / 128, P_), 256>>>(v_int);        // int8 IMMA traces
    wm_loss_kernel<<<dim3(B_ / 64, D_ / 64), 256>>>(thetas);      // ||g||^2 parts
    final_partial<<<16, 256>>>(pN);
    final_sum<<<1, 32>>>(out);
}

// round 15
// speedup vs baseline: 1.5654x; 1.5654x over previous
#include <cuda_runtime.h>
#include <cuda_bf16.h>
#include <cstdint>

// Problem constants (match reference)
static constexpr int B_ = 4096;   // batch
static constexpr int D_ = 512;    // theta dim
static constexpr int K_ = 128;    // mixture comps
static constexpr int A_ = 32;     // alpha dim
static constexpr int P_ = 16;     // hutchinson probes
static constexpr int DT_ = D_ / 64; // d-tiles in wm_loss (8)

// Scratch (device globals; no allocation allowed)
__device__ float g_mu[K_ * D_];        // mu[k][d]
__device__ float g_muT[D_ * K_];       // mu^T[d][k]
__device__ __align__(16) __nv_bfloat16 g_muhi[K_ * D_];  // bf16(mu)
__device__ __align__(16) __nv_bfloat16 g_mulo[K_ * D_];  // bf16(mu - hi)
__device__ float g_musq[K_];           // ||mu_k||^2
__device__ float g_S[B_ * K_];         // softmax weights
__device__ float g_traceP[P_][B_];     // per-probe  sum_k w y^2 - (sum_k w y)^2
__device__ float g_lossPart[DT_][B_];  // per-d-tile sum_d (m - theta)^2
__device__ double g_part[16];          // final partial sums

// ================= portable PTX helpers (no 'a'-gated features) =============
__device__ __forceinline__ uint32_t smem_u32(const void* p) {
    uint32_t a;
    asm("{ .reg .u64 t; cvta.to.shared.u64 t, %1; cvt.u32.u64 %0, t; }"
        : "=r"(a) : "l"(p));
    return a;
}
__device__ __forceinline__ void ldsm_x4(uint32_t& r0, uint32_t& r1, uint32_t& r2,
                                        uint32_t& r3, uint32_t addr) {
    asm volatile("ldmatrix.sync.aligned.m8n8.x4.shared.b16 {%0,%1,%2,%3}, [%4];"
                 : "=r"(r0), "=r"(r1), "=r"(r2), "=r"(r3) : "r"(addr));
}
__device__ __forceinline__ void ldsm_x2(uint32_t& r0, uint32_t& r1, uint32_t addr) {
    asm volatile("ldmatrix.sync.aligned.m8n8.x2.shared.b16 {%0,%1}, [%2];"
                 : "=r"(r0), "=r"(r1) : "r"(addr));
}
__device__ __forceinline__ void mma_bf16(float* c, uint32_t a0, uint32_t a1,
                                         uint32_t a2, uint32_t a3,
                                         uint32_t b0, uint32_t b1) {
    asm volatile(
        "mma.sync.aligned.m16n8k16.row.col.f32.bf16.bf16.f32 "
        "{%0,%1,%2,%3}, {%4,%5,%6,%7}, {%8,%9}, {%0,%1,%2,%3};"
        : "+f"(c[0]), "+f"(c[1]), "+f"(c[2]), "+f"(c[3])
        : "r"(a0), "r"(a1), "r"(a2), "r"(a3), "r"(b0), "r"(b1));
}
// 64B-row swizzle: XOR 16B-unit index with bits [8:7] of the byte offset
__device__ __forceinline__ uint32_t sw64(uint32_t o) { return o ^ ((o >> 3) & 0x30u); }

// ---------------- packed f32x2 helpers (FFMA2 path, logits GEMM) -------------
__device__ __forceinline__ unsigned long long ffma2(unsigned long long a,
                                                    unsigned long long b,
                                                    unsigned long long c) {
    unsigned long long d;
    asm("fma.rn.f32x2 %0, %1, %2, %3;" : "=l"(d) : "l"(a), "l"(b), "l"(c));
    return d;
}
__device__ __forceinline__ void unpack2(unsigned long long v, float& lo, float& hi) {
    asm("mov.b64 {%0, %1}, %2;" : "=f"(lo), "=f"(hi) : "l"(v));
}

// ---------------- K1: mu = alpha @ W, mu^T, ||mu_k||^2, bf16 hi/lo -----------
__global__ void __launch_bounds__(128) mu_kernel(const float* __restrict__ alpha,
                                                 const float* __restrict__ W) {
    int k = blockIdx.x;
    int t = threadIdx.x;
    __shared__ float as[A_];
    if (t < A_) as[t] = alpha[k * A_ + t];
    __syncthreads();
    float sq = 0.f;
#pragma unroll
    for (int rep = 0; rep < D_ / 128; rep++) {
        int d = rep * 128 + t;
        float acc = 0.f;
#pragma unroll
        for (int a = 0; a < A_; a++) acc = fmaf(as[a], W[a * D_ + d], acc);
        g_mu[k * D_ + d] = acc;
        g_muT[(size_t)d * K_ + k] = acc;
        __nv_bfloat16 hi = __float2bfloat16(acc);
        g_muhi[k * D_ + d] = hi;
        g_mulo[k * D_ + d] = __float2bfloat16(acc - __bfloat162float(hi));
        sq = fmaf(acc, acc, sq);
    }
    __shared__ float red[4];
#pragma unroll
    for (int off = 16; off; off >>= 1) sq += __shfl_xor_sync(0xffffffffu, sq, off);
    if ((t & 31) == 0) red[t >> 5] = sq;
    __syncthreads();
    if (t == 0) g_musq[k] = red[0] + red[1] + red[2] + red[3];
}

// ---------------- K2: theta @ mu^T + fused row softmax -> g_S ----------------
__global__ void __launch_bounds__(256)
logits_softmax_kernel(const float* __restrict__ X) {
    __shared__ float2 As2[64][37];
    __shared__ float  Bs[32][128];
    __shared__ float  musq_s[K_];

    const int rowbase = blockIdx.x * 64;
    const int tid = threadIdx.x;
    const int tx = tid & 15;
    const int ty = tid >> 4;
    if (tid < K_) musq_s[tid] = g_musq[tid];

    unsigned long long acc[4][4];
#pragma unroll
    for (int i = 0; i < 4; i++)
#pragma unroll
        for (int j = 0; j < 4; j++) acc[i][j] = 0ull;

    for (int d0 = 0; d0 < D_; d0 += 32) {
#pragma unroll
        for (int it = 0; it < 2; it++) {
            int idx = tid + it * 256;
            int r = idx >> 3;
            int c4 = (idx & 7) << 2;
            float4 va = *(const float4*)(X + (size_t)(rowbase + r) * D_ + d0 + c4);
            As2[r][c4 + 0] = make_float2(va.x, va.x);
            As2[r][c4 + 1] = make_float2(va.y, va.y);
            As2[r][c4 + 2] = make_float2(va.z, va.z);
            As2[r][c4 + 3] = make_float2(va.w, va.w);
        }
#pragma unroll
        for (int it = 0; it < 4; it++) {
            int idx = tid + it * 256;
            int kk = idx >> 5;
            int n4 = (idx & 31) << 2;
            *(float4*)&Bs[kk][n4] = *(const float4*)(g_muT + (size_t)(d0 + kk) * K_ + n4);
        }
        __syncthreads();
#pragma unroll 8
        for (int kk = 0; kk < 32; kk++) {
            ulonglong2 b01 = *(const ulonglong2*)&Bs[kk][tx * 8];
            ulonglong2 b23 = *(const ulonglong2*)&Bs[kk][tx * 8 + 4];
#pragma unroll
            for (int i = 0; i < 4; i++) {
                unsigned long long aa = *(const unsigned long long*)&As2[ty * 4 + i][kk];
                acc[i][0] = ffma2(aa, b01.x, acc[i][0]);
                acc[i][1] = ffma2(aa, b01.y, acc[i][1]);
                acc[i][2] = ffma2(aa, b23.x, acc[i][2]);
                acc[i][3] = ffma2(aa, b23.y, acc[i][3]);
            }
        }
        __syncthreads();
    }

    // Fused softmax: each row's 128 logits live in the 16-lane tx group.
#pragma unroll
    for (int i = 0; i < 4; i++) {
        int row = rowbase + ty * 4 + i;
        float l[8];
#pragma unroll
        for (int j = 0; j < 4; j++) unpack2(acc[i][j], l[2 * j], l[2 * j + 1]);
#pragma unroll
        for (int j = 0; j < 8; j++) l[j] -= 0.5f * musq_s[tx * 8 + j];
        float m = l[0];
#pragma unroll
        for (int j = 1; j < 8; j++) m = fmaxf(m, l[j]);
#pragma unroll
        for (int off = 8; off; off >>= 1) m = fmaxf(m, __shfl_xor_sync(0xffffffffu, m, off));
        float e[8], s = 0.f;
#pragma unroll
        for (int j = 0; j < 8; j++) { e[j] = expf(l[j] - m); s += e[j]; }
#pragma unroll
        for (int off = 8; off; off >>= 1) s += __shfl_xor_sync(0xffffffffu, s, off);
        float inv = 1.0f / s;
        float4 w0 = make_float4(e[0] * inv, e[1] * inv, e[2] * inv, e[3] * inv);
        float4 w1 = make_float4(e[4] * inv, e[5] * inv, e[6] * inv, e[7] * inv);
        *(float4*)&g_S[(size_t)row * K_ + tx * 8 + 0] = w0;
        *(float4*)&g_S[(size_t)row * K_ + tx * 8 + 4] = w1;
    }
}

// ---------------- K3: probe trace via mma.sync bf16 (hi/lo split) ------------
// One CTA: probe p, 128 rows x 128 comps, K=512 in 16 chunks of 32.
// 8 warps: wm = wid&3 (rows 32*wm), wn = wid>>2 (cols 64*wn).  (R9-proven)
static constexpr int BK = 32;                 // d per chunk (64B bf16 rows)
static constexpr int NCH = D_ / BK;           // 16
static constexpr int TILE = 128 * BK * 2;     // 8 KB per operand tile

__global__ void __launch_bounds__(256)
probe_mma_kernel(const int* __restrict__ Vint) {
    __shared__ __align__(1024) char smA[TILE];
    __shared__ __align__(1024) char smBh[TILE];
    __shared__ __align__(1024) char smBl[TILE];
    __shared__ float red1[128], red2[128];

    const int tid = threadIdx.x, wid = tid >> 5, lane = tid & 31;
    const int wm = wid & 3, wn = wid >> 2;
    const int g = lane >> 2, tig = lane & 3;
    const int p = blockIdx.y, rowbase = blockIdx.x * 128;
    const size_t vbase = (size_t)p * B_ * D_ + (size_t)rowbase * D_;

    const uint32_t aBase = smem_u32(smA);
    const uint32_t bhBase = smem_u32(smBh);
    const uint32_t blBase = smem_u32(smBl);

    // Precompute ldmatrix lane addresses (byte offsets before k-step shift)
    const int ami = lane >> 3;                     // 0..3
    const uint32_t aRowOff[2] = {
        (uint32_t)((wm * 32 + 0 * 16 + (ami & 1) * 8 + (lane & 7)) * 64 + (ami >> 1) * 16),
        (uint32_t)((wm * 32 + 1 * 16 + (ami & 1) * 8 + (lane & 7)) * 64 + (ami >> 1) * 16)};
    const int bmi = (lane >> 3) & 1;
    const uint32_t bRowOff0 = (uint32_t)((wn * 64 + (lane & 7)) * 64 + bmi * 16);

    float acc[2][8][4];
#pragma unroll
    for (int i = 0; i < 2; i++)
#pragma unroll
        for (int j = 0; j < 8; j++)
#pragma unroll
            for (int q = 0; q < 4; q++) acc[i][j][q] = 0.f;

    // Prologue: A ints for chunk 0
    int4 R[4];
#pragma unroll
    for (int i = 0; i < 4; i++) {
        int u = tid + i * 256;
        R[i] = *(const int4*)(Vint + vbase + (size_t)(u >> 3) * D_ + ((u & 7) << 2));
    }

    for (int ch = 0; ch < NCH; ch++) {
        __syncthreads();   // previous chunk's mma done before overwriting tiles
        // B tiles: LDG + swizzled STS (L2-resident, 2x uint4 per matrix)
#pragma unroll
        for (int i = 0; i < 2; i++) {
            int u = tid + i * 256;           // 0..511 (128 rows x 4 16B-units)
            int n = u >> 2, c16 = u & 3;
            uint4 vh = *(const uint4*)(g_muhi + (size_t)n * D_ + ch * BK + c16 * 8);
            uint4 vl = *(const uint4*)(g_mulo + (size_t)n * D_ + ch * BK + c16 * 8);
            uint32_t off = sw64((uint32_t)(n * 64 + c16 * 16));
            *(uint4*)(smBh + off) = vh;
            *(uint4*)(smBl + off) = vl;
        }
        // A tile: convert staged ints -> bf16 +-1, swizzled 8B stores
#pragma unroll
        for (int i = 0; i < 4; i++) {
            int u = tid + i * 256;           // 0..1023 (128 rows x 8 8B-units)
            int r = u >> 3, c8 = u & 7;
            uint32_t w0 = 0xBF80BF80u ^ ((uint32_t)R[i].x << 15) ^ ((uint32_t)R[i].y << 31);
            uint32_t w1 = 0xBF80BF80u ^ ((uint32_t)R[i].z << 15) ^ ((uint32_t)R[i].w << 31);
            *(uint2*)(smA + sw64((uint32_t)(r * 64 + c8 * 8))) = make_uint2(w0, w1);
        }
        // Prefetch next chunk's A ints (in flight during the MMA stage)
        if (ch + 1 < NCH) {
#pragma unroll
            for (int i = 0; i < 4; i++) {
                int u = tid + i * 256;
                R[i] = *(const int4*)(Vint + vbase + (size_t)(u >> 3) * D_ +
                                      (ch + 1) * BK + ((u & 7) << 2));
            }
        }
        __syncthreads();
        // MMA stage: 2 k-steps of 16
#pragma unroll
        for (int ks = 0; ks < 2; ks++) {
            uint32_t a0[4], a1[4];
            ldsm_x4(a0[0], a0[1], a0[2], a0[3], aBase + sw64(aRowOff[0] + ks * 32));
            ldsm_x4(a1[0], a1[1], a1[2], a1[3], aBase + sw64(aRowOff[1] + ks * 32));
#pragma unroll
            for (int nf = 0; nf < 8; nf++) {
                uint32_t boff = sw64(bRowOff0 + (uint32_t)(nf * 8 * 64) + ks * 32);
                uint32_t b0, b1;
                ldsm_x2(b0, b1, bhBase + boff);
                mma_bf16(acc[0][nf], a0[0], a0[1], a0[2], a0[3], b0, b1);
                mma_bf16(acc[1][nf], a1[0], a1[1], a1[2], a1[3], b0, b1);
                ldsm_x2(b0, b1, blBase + boff);
                mma_bf16(acc[0][nf], a0[0], a0[1], a0[2], a0[3], b0, b1);
                mma_bf16(acc[1][nf], a1[0], a1[1], a1[2], a1[3], b0, b1);
            }
        }
    }

    // Epilogue: per-row trace terms s1 = sum w y^2, s2 = sum w y
    float s1[2][2] = {{0.f, 0.f}, {0.f, 0.f}};
    float s2[2][2] = {{0.f, 0.f}, {0.f, 0.f}};
#pragma unroll
    for (int mf = 0; mf < 2; mf++) {
        int r0 = rowbase + wm * 32 + mf * 16 + g;
#pragma unroll
        for (int nf = 0; nf < 8; nf++) {
            int col = wn * 64 + nf * 8 + tig * 2;
            float2 w0 = __ldg((const float2*)&g_S[(size_t)r0 * K_ + col]);
            float2 w1 = __ldg((const float2*)&g_S[(size_t)(r0 + 8) * K_ + col]);
            float c0 = acc[mf][nf][0], c1 = acc[mf][nf][1];
            float c2 = acc[mf][nf][2], c3 = acc[mf][nf][3];
            s1[mf][0] = fmaf(w0.x * c0, c0, fmaf(w0.y * c1, c1, s1[mf][0]));
            s2[mf][0] = fmaf(w0.x, c0, fmaf(w0.y, c1, s2[mf][0]));
            s1[mf][1] = fmaf(w1.x * c2, c2, fmaf(w1.y * c3, c3, s1[mf][1]));
            s2[mf][1] = fmaf(w1.x, c2, fmaf(w1.y, c3, s2[mf][1]));
        }
    }
    // reduce across the 4 tig lanes
#pragma unroll
    for (int mf = 0; mf < 2; mf++)
#pragma unroll
        for (int h = 0; h < 2; h++)
#pragma unroll
            for (int off = 1; off < 4; off <<= 1) {
                s1[mf][h] += __shfl_xor_sync(0xffffffffu, s1[mf][h], off);
                s2[mf][h] += __shfl_xor_sync(0xffffffffu, s2[mf][h], off);
            }
    __syncthreads();   // all warps done with SMEM tiles + values ready
    if (wn == 1 && tig == 0) {
#pragma unroll
        for (int mf = 0; mf < 2; mf++)
#pragma unroll
            for (int h = 0; h < 2; h++) {
                int rl = wm * 32 + mf * 16 + h * 8 + g;
                red1[rl] = s1[mf][h];
                red2[rl] = s2[mf][h];
            }
    }
    __syncthreads();
    if (wn == 0 && tig == 0) {
#pragma unroll
        for (int mf = 0; mf < 2; mf++)
#pragma unroll
            for (int h = 0; h < 2; h++) {
                int rl = wm * 32 + mf * 16 + h * 8 + g;
                float t1 = s1[mf][h] + red1[rl];
                float t2 = s2[mf][h] + red2[rl];
                g_traceP[p][rowbase + rl] = t1 - t2 * t2;
            }
    }
}

// ---------------- K4: M = w @ mu, fused sum_d (m - theta)^2 (R9-proven) ------
__global__ void __launch_bounds__(256)
wm_loss_kernel(const float* __restrict__ theta) {
    __shared__ float Ws[64][36];
    __shared__ float Ms[32][68];

    const int rowbase = blockIdx.x * 64;
    const int d0 = blockIdx.y * 64;
    const int tid = threadIdx.x;
    const int tx = tid & 15;
    const int ty = tid >> 4;

    float acc[4][4];
#pragma unroll
    for (int i = 0; i < 4; i++)
#pragma unroll
        for (int j = 0; j < 4; j++) acc[i][j] = 0.f;

    for (int k0 = 0; k0 < K_; k0 += 32) {
#pragma unroll
        for (int it = 0; it < 2; it++) {
            int idx = tid + it * 256;
            int r = idx >> 3;
            int c4 = (idx & 7) << 2;
            *(float4*)&Ws[r][c4] = *(const float4*)&g_S[(size_t)(rowbase + r) * K_ + k0 + c4];
        }
#pragma unroll
        for (int it = 0; it < 2; it++) {
            int idx = tid + it * 256;
            int kk = idx >> 4;
            int c4 = (idx & 15) << 2;
            *(float4*)&Ms[kk][c4] = *(const float4*)&g_mu[(size_t)(k0 + kk) * D_ + d0 + c4];
        }
        __syncthreads();
#pragma unroll 8
        for (int kk = 0; kk < 32; kk++) {
            float a[4], bb[4];
#pragma unroll
            for (int i = 0; i < 4; i++) a[i] = Ws[ty * 4 + i][kk];
#pragma unroll
            for (int j = 0; j < 4; j++) bb[j] = Ms[kk][tx * 4 + j];
#pragma unroll
            for (int i = 0; i < 4; i++)
#pragma unroll
                for (int j = 0; j < 4; j++) acc[i][j] = fmaf(a[i], bb[j], acc[i][j]);
        }
        __syncthreads();
    }

#pragma unroll
    for (int i = 0; i < 4; i++) {
        int row = rowbase + ty * 4 + i;
        float s = 0.f;
#pragma unroll
        for (int j = 0; j < 4; j++) {
            float th = theta[(size_t)row * D_ + d0 + tx * 4 + j];
            float df = acc[i][j] - th;
            s = fmaf(df, df, s);
        }
#pragma unroll
        for (int off = 8; off; off >>= 1) s += __shfl_xor_sync(0xffffffffu, s, off);
        if (tx == 0) g_lossPart[blockIdx.y][row] = s;
    }
}

// ---------------- K5/K6: two-stage final reduction (only change vs R9) -------
__global__ void __launch_bounds__(256)
final_partial(const int* __restrict__ pN) {
    int b = blockIdx.x * 256 + threadIdx.x;
    float Nf = (float)pN[0];
    float temper = Nf / (Nf + 1.0f);
    float tr = 0.f;
#pragma unroll
    for (int p = 0; p < P_; p++) tr += g_traceP[p][b];
    float ls = 0.f;
#pragma unroll
    for (int dt = 0; dt < DT_; dt++) ls += g_lossPart[dt][b];
    double val = (double)(0.5f * temper * temper * ls
                          + temper * (tr * (1.0f / (float)P_) - (float)D_));
    __shared__ double sd[256];
    int t = threadIdx.x;
    sd[t] = val;
    __syncthreads();
    for (int s = 128; s; s >>= 1) {
        if (t < s) sd[t] += sd[t + s];
        __syncthreads();
    }
    if (t == 0) g_part[blockIdx.x] = sd[0];
}

__global__ void final_sum(float* __restrict__ out) {
    if (threadIdx.x == 0) {
        double acc = 0.0;
#pragma unroll
        for (int i = 0; i < 16; i++) acc += g_part[i];
        out[0] = (float)(acc / (double)B_);
    }
}

// ---------------- launch ------------------------------------------------------
extern "C" void kernel_launch(void* const* d_in, const int* in_sizes, int n_in,
                              void* d_out, int out_size) {
    const float* thetas = (const float*)d_in[0];  // [B, D]
    const float* alpha  = (const float*)d_in[1];  // [K, A]
    const float* W      = (const float*)d_in[2];  // [A, D]
    const int*   v_int  = (const int*)d_in[3];    // [P, B, D]
    const int*   pN     = (const int*)d_in[4];    // N_dataset
    float* out = (float*)d_out;

    mu_kernel<<<K_, 128>>>(alpha, W);
    logits_softmax_kernel<<<B_ / 64, 256>>>(thetas);              // logits + softmax
    probe_mma_kernel<<<dim3(B_ / 128, P_), 256>>>(v_int);         // HMMA traces (R9)
    wm_loss_kernel<<<dim3(B_ / 64, D_ / 64), 256>>>(thetas);      // ||g||^2 parts
    final_partial<<<16, 256>>>(pN);
    final_sum<<<1, 32>>>(out);
}

// round 16
// speedup vs baseline: 1.9457x; 1.2430x over previous
#include <cuda_runtime.h>
#include <cuda_bf16.h>
#include <cstdint>

// Problem constants (match reference)
static constexpr int B_ = 4096;   // batch
static constexpr int D_ = 512;    // theta dim
static constexpr int K_ = 128;    // mixture comps
static constexpr int A_ = 32;     // alpha dim
static constexpr int P_ = 16;     // hutchinson probes
static constexpr int DT_ = D_ / 64; // d-tiles in wm_loss (8)

// Scratch (device globals; no allocation allowed)
__device__ float g_mu[K_ * D_];        // mu[k][d]
__device__ float g_muT[D_ * K_];       // mu^T[d][k]
__device__ __align__(16) __nv_bfloat16 g_muhi[K_ * D_];  // bf16(mu)
__device__ float g_musq[K_];           // ||mu_k||^2
__device__ float g_S[B_ * K_];         // softmax weights
__device__ float g_traceP[P_][B_];     // per-probe  sum_k w y^2 - (sum_k w y)^2
__device__ float g_lossPart[DT_][B_];  // per-d-tile sum_d (m - theta)^2
__device__ double g_part[16];          // final partial sums

// ================= portable PTX helpers (no 'a'-gated features) =============
__device__ __forceinline__ uint32_t smem_u32(const void* p) {
    uint32_t a;
    asm("{ .reg .u64 t; cvta.to.shared.u64 t, %1; cvt.u32.u64 %0, t; }"
        : "=r"(a) : "l"(p));
    return a;
}
__device__ __forceinline__ void ldsm_x4(uint32_t& r0, uint32_t& r1, uint32_t& r2,
                                        uint32_t& r3, uint32_t addr) {
    asm volatile("ldmatrix.sync.aligned.m8n8.x4.shared.b16 {%0,%1,%2,%3}, [%4];"
                 : "=r"(r0), "=r"(r1), "=r"(r2), "=r"(r3) : "r"(addr));
}
__device__ __forceinline__ void ldsm_x2(uint32_t& r0, uint32_t& r1, uint32_t addr) {
    asm volatile("ldmatrix.sync.aligned.m8n8.x2.shared.b16 {%0,%1}, [%2];"
                 : "=r"(r0), "=r"(r1) : "r"(addr));
}
__device__ __forceinline__ void mma_bf16(float* c, uint32_t a0, uint32_t a1,
                                         uint32_t a2, uint32_t a3,
                                         uint32_t b0, uint32_t b1) {
    asm volatile(
        "mma.sync.aligned.m16n8k16.row.col.f32.bf16.bf16.f32 "
        "{%0,%1,%2,%3}, {%4,%5,%6,%7}, {%8,%9}, {%0,%1,%2,%3};"
        : "+f"(c[0]), "+f"(c[1]), "+f"(c[2]), "+f"(c[3])
        : "r"(a0), "r"(a1), "r"(a2), "r"(a3), "r"(b0), "r"(b1));
}
// 64B-row swizzle: XOR 16B-unit index with bits [8:7] of the byte offset
__device__ __forceinline__ uint32_t sw64(uint32_t o) { return o ^ ((o >> 3) & 0x30u); }

// ---------------- packed f32x2 helpers (FFMA2 path, logits GEMM) -------------
__device__ __forceinline__ unsigned long long ffma2(unsigned long long a,
                                                    unsigned long long b,
                                                    unsigned long long c) {
    unsigned long long d;
    asm("fma.rn.f32x2 %0, %1, %2, %3;" : "=l"(d) : "l"(a), "l"(b), "l"(c));
    return d;
}
__device__ __forceinline__ void unpack2(unsigned long long v, float& lo, float& hi) {
    asm("mov.b64 {%0, %1}, %2;" : "=f"(lo), "=f"(hi) : "l"(v));
}

// ---------------- K1: mu = alpha @ W, mu^T, ||mu_k||^2, bf16 ----------------
__global__ void __launch_bounds__(128) mu_kernel(const float* __restrict__ alpha,
                                                 const float* __restrict__ W) {
    int k = blockIdx.x;
    int t = threadIdx.x;
    __shared__ float as[A_];
    if (t < A_) as[t] = alpha[k * A_ + t];
    __syncthreads();
    float sq = 0.f;
#pragma unroll
    for (int rep = 0; rep < D_ / 128; rep++) {
        int d = rep * 128 + t;
        float acc = 0.f;
#pragma unroll
        for (int a = 0; a < A_; a++) acc = fmaf(as[a], W[a * D_ + d], acc);
        g_mu[k * D_ + d] = acc;
        g_muT[(size_t)d * K_ + k] = acc;
        g_muhi[k * D_ + d] = __float2bfloat16(acc);
        sq = fmaf(acc, acc, sq);
    }
    __shared__ float red[4];
#pragma unroll
    for (int off = 16; off; off >>= 1) sq += __shfl_xor_sync(0xffffffffu, sq, off);
    if ((t & 31) == 0) red[t >> 5] = sq;
    __syncthreads();
    if (t == 0) g_musq[k] = red[0] + red[1] + red[2] + red[3];
}

// ---------------- K2: theta @ mu^T + fused row softmax -> g_S ----------------
__global__ void __launch_bounds__(256)
logits_softmax_kernel(const float* __restrict__ X) {
    __shared__ float2 As2[64][37];
    __shared__ float  Bs[32][128];
    __shared__ float  musq_s[K_];

    const int rowbase = blockIdx.x * 64;
    const int tid = threadIdx.x;
    const int tx = tid & 15;
    const int ty = tid >> 4;
    if (tid < K_) musq_s[tid] = g_musq[tid];

    unsigned long long acc[4][4];
#pragma unroll
    for (int i = 0; i < 4; i++)
#pragma unroll
        for (int j = 0; j < 4; j++) acc[i][j] = 0ull;

    for (int d0 = 0; d0 < D_; d0 += 32) {
#pragma unroll
        for (int it = 0; it < 2; it++) {
            int idx = tid + it * 256;
            int r = idx >> 3;
            int c4 = (idx & 7) << 2;
            float4 va = *(const float4*)(X + (size_t)(rowbase + r) * D_ + d0 + c4);
            As2[r][c4 + 0] = make_float2(va.x, va.x);
            As2[r][c4 + 1] = make_float2(va.y, va.y);
            As2[r][c4 + 2] = make_float2(va.z, va.z);
            As2[r][c4 + 3] = make_float2(va.w, va.w);
        }
#pragma unroll
        for (int it = 0; it < 4; it++) {
            int idx = tid + it * 256;
            int kk = idx >> 5;
            int n4 = (idx & 31) << 2;
            *(float4*)&Bs[kk][n4] = *(const float4*)(g_muT + (size_t)(d0 + kk) * K_ + n4);
        }
        __syncthreads();
#pragma unroll 8
        for (int kk = 0; kk < 32; kk++) {
            ulonglong2 b01 = *(const ulonglong2*)&Bs[kk][tx * 8];
            ulonglong2 b23 = *(const ulonglong2*)&Bs[kk][tx * 8 + 4];
#pragma unroll
            for (int i = 0; i < 4; i++) {
                unsigned long long aa = *(const unsigned long long*)&As2[ty * 4 + i][kk];
                acc[i][0] = ffma2(aa, b01.x, acc[i][0]);
                acc[i][1] = ffma2(aa, b01.y, acc[i][1]);
                acc[i][2] = ffma2(aa, b23.x, acc[i][2]);
                acc[i][3] = ffma2(aa, b23.y, acc[i][3]);
            }
        }
        __syncthreads();
    }

    // Fused softmax: each row's 128 logits live in the 16-lane tx group.
#pragma unroll
    for (int i = 0; i < 4; i++) {
        int row = rowbase + ty * 4 + i;
        float l[8];
#pragma unroll
        for (int j = 0; j < 4; j++) unpack2(acc[i][j], l[2 * j], l[2 * j + 1]);
#pragma unroll
        for (int j = 0; j < 8; j++) l[j] -= 0.5f * musq_s[tx * 8 + j];
        float m = l[0];
#pragma unroll
        for (int j = 1; j < 8; j++) m = fmaxf(m, l[j]);
#pragma unroll
        for (int off = 8; off; off >>= 1) m = fmaxf(m, __shfl_xor_sync(0xffffffffu, m, off));
        float e[8], s = 0.f;
#pragma unroll
        for (int j = 0; j < 8; j++) { e[j] = expf(l[j] - m); s += e[j]; }
#pragma unroll
        for (int off = 8; off; off >>= 1) s += __shfl_xor_sync(0xffffffffu, s, off);
        float inv = 1.0f / s;
        float4 w0 = make_float4(e[0] * inv, e[1] * inv, e[2] * inv, e[3] * inv);
        float4 w1 = make_float4(e[4] * inv, e[5] * inv, e[6] * inv, e[7] * inv);
        *(float4*)&g_S[(size_t)row * K_ + tx * 8 + 0] = w0;
        *(float4*)&g_S[(size_t)row * K_ + tx * 8 + 4] = w1;
    }
}

// ---------------- K3: probe trace via mma.sync bf16 (single-term B) ----------
// One CTA: probe p, 128 rows x 128 comps, K=512 in 16 chunks of 32.
// 8 warps: wm = wid&3 (rows 32*wm), wn = wid>>2 (cols 64*wn).
// Only change vs R15: the mu_lo correction stream is removed (2x fewer MMA).
static constexpr int BK = 32;                 // d per chunk (64B bf16 rows)
static constexpr int NCH = D_ / BK;           // 16
static constexpr int TILE = 128 * BK * 2;     // 8 KB per operand tile

__global__ void __launch_bounds__(256)
probe_mma_kernel(const int* __restrict__ Vint) {
    __shared__ __align__(1024) char smA[TILE];
    __shared__ __align__(1024) char smBh[TILE];
    __shared__ float red1[128], red2[128];

    const int tid = threadIdx.x, wid = tid >> 5, lane = tid & 31;
    const int wm = wid & 3, wn = wid >> 2;
    const int g = lane >> 2, tig = lane & 3;
    const int p = blockIdx.y, rowbase = blockIdx.x * 128;
    const size_t vbase = (size_t)p * B_ * D_ + (size_t)rowbase * D_;

    const uint32_t aBase = smem_u32(smA);
    const uint32_t bhBase = smem_u32(smBh);

    // Precompute ldmatrix lane addresses (byte offsets before k-step shift)
    const int ami = lane >> 3;                     // 0..3
    const uint32_t aRowOff[2] = {
        (uint32_t)((wm * 32 + 0 * 16 + (ami & 1) * 8 + (lane & 7)) * 64 + (ami >> 1) * 16),
        (uint32_t)((wm * 32 + 1 * 16 + (ami & 1) * 8 + (lane & 7)) * 64 + (ami >> 1) * 16)};
    const int bmi = (lane >> 3) & 1;
    const uint32_t bRowOff0 = (uint32_t)((wn * 64 + (lane & 7)) * 64 + bmi * 16);

    float acc[2][8][4];
#pragma unroll
    for (int i = 0; i < 2; i++)
#pragma unroll
        for (int j = 0; j < 8; j++)
#pragma unroll
            for (int q = 0; q < 4; q++) acc[i][j][q] = 0.f;

    // Prologue: A ints for chunk 0
    int4 R[4];
#pragma unroll
    for (int i = 0; i < 4; i++) {
        int u = tid + i * 256;
        R[i] = *(const int4*)(Vint + vbase + (size_t)(u >> 3) * D_ + ((u & 7) << 2));
    }

    for (int ch = 0; ch < NCH; ch++) {
        __syncthreads();   // previous chunk's mma done before overwriting tiles
        // B tile: LDG + swizzled STS (L2-resident, 2x uint4)
#pragma unroll
        for (int i = 0; i < 2; i++) {
            int u = tid + i * 256;           // 0..511 (128 rows x 4 16B-units)
            int n = u >> 2, c16 = u & 3;
            uint4 vh = *(const uint4*)(g_muhi + (size_t)n * D_ + ch * BK + c16 * 8);
            *(uint4*)(smBh + sw64((uint32_t)(n * 64 + c16 * 16))) = vh;
        }
        // A tile: convert staged ints -> bf16 +-1, swizzled 8B stores
#pragma unroll
        for (int i = 0; i < 4; i++) {
            int u = tid + i * 256;           // 0..1023 (128 rows x 8 8B-units)
            int r = u >> 3, c8 = u & 7;
            uint32_t w0 = 0xBF80BF80u ^ ((uint32_t)R[i].x << 15) ^ ((uint32_t)R[i].y << 31);
            uint32_t w1 = 0xBF80BF80u ^ ((uint32_t)R[i].z << 15) ^ ((uint32_t)R[i].w << 31);
            *(uint2*)(smA + sw64((uint32_t)(r * 64 + c8 * 8))) = make_uint2(w0, w1);
        }
        // Prefetch next chunk's A ints (in flight during the MMA stage)
        if (ch + 1 < NCH) {
#pragma unroll
            for (int i = 0; i < 4; i++) {
                int u = tid + i * 256;
                R[i] = *(const int4*)(Vint + vbase + (size_t)(u >> 3) * D_ +
                                      (ch + 1) * BK + ((u & 7) << 2));
            }
        }
        __syncthreads();
        // MMA stage: 2 k-steps of 16
#pragma unroll
        for (int ks = 0; ks < 2; ks++) {
            uint32_t a0[4], a1[4];
            ldsm_x4(a0[0], a0[1], a0[2], a0[3], aBase + sw64(aRowOff[0] + ks * 32));
            ldsm_x4(a1[0], a1[1], a1[2], a1[3], aBase + sw64(aRowOff[1] + ks * 32));
#pragma unroll
            for (int nf = 0; nf < 8; nf++) {
                uint32_t boff = sw64(bRowOff0 + (uint32_t)(nf * 8 * 64) + ks * 32);
                uint32_t b0, b1;
                ldsm_x2(b0, b1, bhBase + boff);
                mma_bf16(acc[0][nf], a0[0], a0[1], a0[2], a0[3], b0, b1);
                mma_bf16(acc[1][nf], a1[0], a1[1], a1[2], a1[3], b0, b1);
            }
        }
    }

    // Epilogue: per-row trace terms s1 = sum w y^2, s2 = sum w y
    float s1[2][2] = {{0.f, 0.f}, {0.f, 0.f}};
    float s2[2][2] = {{0.f, 0.f}, {0.f, 0.f}};
#pragma unroll
    for (int mf = 0; mf < 2; mf++) {
        int r0 = rowbase + wm * 32 + mf * 16 + g;
#pragma unroll
        for (int nf = 0; nf < 8; nf++) {
            int col = wn * 64 + nf * 8 + tig * 2;
            float2 w0 = __ldg((const float2*)&g_S[(size_t)r0 * K_ + col]);
            float2 w1 = __ldg((const float2*)&g_S[(size_t)(r0 + 8) * K_ + col]);
            float c0 = acc[mf][nf][0], c1 = acc[mf][nf][1];
            float c2 = acc[mf][nf][2], c3 = acc[mf][nf][3];
            s1[mf][0] = fmaf(w0.x * c0, c0, fmaf(w0.y * c1, c1, s1[mf][0]));
            s2[mf][0] = fmaf(w0.x, c0, fmaf(w0.y, c1, s2[mf][0]));
            s1[mf][1] = fmaf(w1.x * c2, c2, fmaf(w1.y * c3, c3, s1[mf][1]));
            s2[mf][1] = fmaf(w1.x, c2, fmaf(w1.y, c3, s2[mf][1]));
        }
    }
    // reduce across the 4 tig lanes
#pragma unroll
    for (int mf = 0; mf < 2; mf++)
#pragma unroll
        for (int h = 0; h < 2; h++)
#pragma unroll
            for (int off = 1; off < 4; off <<= 1) {
                s1[mf][h] += __shfl_xor_sync(0xffffffffu, s1[mf][h], off);
                s2[mf][h] += __shfl_xor_sync(0xffffffffu, s2[mf][h], off);
            }
    __syncthreads();   // all warps done with SMEM tiles + values ready
    if (wn == 1 && tig == 0) {
#pragma unroll
        for (int mf = 0; mf < 2; mf++)
#pragma unroll
            for (int h = 0; h < 2; h++) {
                int rl = wm * 32 + mf * 16 + h * 8 + g;
                red1[rl] = s1[mf][h];
                red2[rl] = s2[mf][h];
            }
    }
    __syncthreads();
    if (wn == 0 && tig == 0) {
#pragma unroll
        for (int mf = 0; mf < 2; mf++)
#pragma unroll
            for (int h = 0; h < 2; h++) {
                int rl = wm * 32 + mf * 16 + h * 8 + g;
                float t1 = s1[mf][h] + red1[rl];
                float t2 = s2[mf][h] + red2[rl];
                g_traceP[p][rowbase + rl] = t1 - t2 * t2;
            }
    }
}

// ---------------- K4: M = w @ mu, fused sum_d (m - theta)^2 (R9-proven) ------
__global__ void __launch_bounds__(256)
wm_loss_kernel(const float* __restrict__ theta) {
    __shared__ float Ws[64][36];
    __shared__ float Ms[32][68];

    const int rowbase = blockIdx.x * 64;
    const int d0 = blockIdx.y * 64;
    const int tid = threadIdx.x;
    const int tx = tid & 15;
    const int ty = tid >> 4;

    float acc[4][4];
#pragma unroll
    for (int i = 0; i < 4; i++)
#pragma unroll
        for (int j = 0; j < 4; j++) acc[i][j] = 0.f;

    for (int k0 = 0; k0 < K_; k0 += 32) {
#pragma unroll
        for (int it = 0; it < 2; it++) {
            int idx = tid + it * 256;
            int r = idx >> 3;
            int c4 = (idx & 7) << 2;
            *(float4*)&Ws[r][c4] = *(const float4*)&g_S[(size_t)(rowbase + r) * K_ + k0 + c4];
        }
#pragma unroll
        for (int it = 0; it < 2; it++) {
            int idx = tid + it * 256;
            int kk = idx >> 4;
            int c4 = (idx & 15) << 2;
            *(float4*)&Ms[kk][c4] = *(const float4*)&g_mu[(size_t)(k0 + kk) * D_ + d0 + c4];
        }
        __syncthreads();
#pragma unroll 8
        for (int kk = 0; kk < 32; kk++) {
            float a[4], bb[4];
#pragma unroll
            for (int i = 0; i < 4; i++) a[i] = Ws[ty * 4 + i][kk];
#pragma unroll
            for (int j = 0; j < 4; j++) bb[j] = Ms[kk][tx * 4 + j];
#pragma unroll
            for (int i = 0; i < 4; i++)
#pragma unroll
                for (int j = 0; j < 4; j++) acc[i][j] = fmaf(a[i], bb[j], acc[i][j]);
        }
        __syncthreads();
    }

#pragma unroll
    for (int i = 0; i < 4; i++) {
        int row = rowbase + ty * 4 + i;
        float s = 0.f;
#pragma unroll
        for (int j = 0; j < 4; j++) {
            float th = theta[(size_t)row * D_ + d0 + tx * 4 + j];
            float df = acc[i][j] - th;
            s = fmaf(df, df, s);
        }
#pragma unroll
        for (int off = 8; off; off >>= 1) s += __shfl_xor_sync(0xffffffffu, s, off);
        if (tx == 0) g_lossPart[blockIdx.y][row] = s;
    }
}

// ---------------- K5/K6: two-stage final reduction ---------------------------
__global__ void __launch_bounds__(256)
final_partial(const int* __restrict__ pN) {
    int b = blockIdx.x * 256 + threadIdx.x;
    float Nf = (float)pN[0];
    float temper = Nf / (Nf + 1.0f);
    float tr = 0.f;
#pragma unroll
    for (int p = 0; p < P_; p++) tr += g_traceP[p][b];
    float ls = 0.f;
#pragma unroll
    for (int dt = 0; dt < DT_; dt++) ls += g_lossPart[dt][b];
    double val = (double)(0.5f * temper * temper * ls
                          + temper * (tr * (1.0f / (float)P_) - (float)D_));
    __shared__ double sd[256];
    int t = threadIdx.x;
    sd[t] = val;
    __syncthreads();
    for (int s = 128; s; s >>= 1) {
        if (t < s) sd[t] += sd[t + s];
        __syncthreads();
    }
    if (t == 0) g_part[blockIdx.x] = sd[0];
}

__global__ void final_sum(float* __restrict__ out) {
    if (threadIdx.x == 0) {
        double acc = 0.0;
#pragma unroll
        for (int i = 0; i < 16; i++) acc += g_part[i];
        out[0] = (float)(acc / (double)B_);
    }
}

// ---------------- launch ------------------------------------------------------
extern "C" void kernel_launch(void* const* d_in, const int* in_sizes, int n_in,
                              void* d_out, int out_size) {
    const float* thetas = (const float*)d_in[0];  // [B, D]
    const float* alpha  = (const float*)d_in[1];  // [K, A]
    const float* W      = (const float*)d_in[2];  // [A, D]
    const int*   v_int  = (const int*)d_in[3];    // [P, B, D]
    const int*   pN     = (const int*)d_in[4];    // N_dataset
    float* out = (float*)d_out;

    mu_kernel<<<K_, 128>>>(alpha, W);
    logits_softmax_kernel<<<B_ / 64, 256>>>(thetas);              // logits + softmax
    probe_mma_kernel<<<dim3(B_ / 128, P_), 256>>>(v_int);         // HMMA traces (single-B)
    wm_loss_kernel<<<dim3(B_ / 64, D_ / 64), 256>>>(thetas);      // ||g||^2 parts
    final_partial<<<16, 256>>>(pN);
    final_sum<<<1, 32>>>(out);
}

// round 17
// speedup vs baseline: 2.2388x; 1.1506x over previous
#include <cuda_runtime.h>
#include <cuda_bf16.h>
#include <cstdint>

// Problem constants (match reference)
static constexpr int B_ = 4096;   // batch
static constexpr int D_ = 512;    // theta dim
static constexpr int K_ = 128;    // mixture comps
static constexpr int A_ = 32;     // alpha dim
static constexpr int P_ = 16;     // hutchinson probes
static constexpr int DT_ = D_ / 64; // d-tiles in wm_loss (8)

// Scratch (device globals; no allocation allowed)
__device__ float g_mu[K_ * D_];        // mu[k][d]
__device__ float g_muT[D_ * K_];       // mu^T[d][k]
__device__ __align__(16) __nv_bfloat16 g_muhi[K_ * D_];  // bf16(mu)
__device__ float g_musq[K_];           // ||mu_k||^2
__device__ float g_S[B_ * K_];         // softmax weights
__device__ float g_traceP[P_][B_];     // per-probe  sum_k w y^2 - (sum_k w y)^2
__device__ float g_lossPart[DT_][B_];  // per-d-tile sum_d (m - theta)^2
__device__ double g_part[16];          // final partial sums

// ================= portable PTX helpers (no 'a'-gated features) =============
__device__ __forceinline__ uint32_t smem_u32(const void* p) {
    uint32_t a;
    asm("{ .reg .u64 t; cvta.to.shared.u64 t, %1; cvt.u32.u64 %0, t; }"
        : "=r"(a) : "l"(p));
    return a;
}
__device__ __forceinline__ void ldsm_x4(uint32_t& r0, uint32_t& r1, uint32_t& r2,
                                        uint32_t& r3, uint32_t addr) {
    asm volatile("ldmatrix.sync.aligned.m8n8.x4.shared.b16 {%0,%1,%2,%3}, [%4];"
                 : "=r"(r0), "=r"(r1), "=r"(r2), "=r"(r3) : "r"(addr));
}
__device__ __forceinline__ void ldsm_x2(uint32_t& r0, uint32_t& r1, uint32_t addr) {
    asm volatile("ldmatrix.sync.aligned.m8n8.x2.shared.b16 {%0,%1}, [%2];"
                 : "=r"(r0), "=r"(r1) : "r"(addr));
}
__device__ __forceinline__ void mma_bf16(float* c, uint32_t a0, uint32_t a1,
                                         uint32_t a2, uint32_t a3,
                                         uint32_t b0, uint32_t b1) {
    asm volatile(
        "mma.sync.aligned.m16n8k16.row.col.f32.bf16.bf16.f32 "
        "{%0,%1,%2,%3}, {%4,%5,%6,%7}, {%8,%9}, {%0,%1,%2,%3};"
        : "+f"(c[0]), "+f"(c[1]), "+f"(c[2]), "+f"(c[3])
        : "r"(a0), "r"(a1), "r"(a2), "r"(a3), "r"(b0), "r"(b1));
}
// 64B-row swizzle: XOR 16B-unit index with bits [8:7] of the byte offset
__device__ __forceinline__ uint32_t sw64(uint32_t o) { return o ^ ((o >> 3) & 0x30u); }

// ---------------- packed f32x2 helpers (FFMA2 path, logits GEMM) -------------
__device__ __forceinline__ unsigned long long ffma2(unsigned long long a,
                                                    unsigned long long b,
                                                    unsigned long long c) {
    unsigned long long d;
    asm("fma.rn.f32x2 %0, %1, %2, %3;" : "=l"(d) : "l"(a), "l"(b), "l"(c));
    return d;
}
__device__ __forceinline__ void unpack2(unsigned long long v, float& lo, float& hi) {
    asm("mov.b64 {%0, %1}, %2;" : "=f"(lo), "=f"(hi) : "l"(v));
}

// ---------------- K1: mu = alpha @ W, mu^T, ||mu_k||^2, bf16 ----------------
__global__ void __launch_bounds__(128) mu_kernel(const float* __restrict__ alpha,
                                                 const float* __restrict__ W) {
    int k = blockIdx.x;
    int t = threadIdx.x;
    __shared__ float as[A_];
    if (t < A_) as[t] = alpha[k * A_ + t];
    __syncthreads();
    float sq = 0.f;
#pragma unroll
    for (int rep = 0; rep < D_ / 128; rep++) {
        int d = rep * 128 + t;
        float acc = 0.f;
#pragma unroll
        for (int a = 0; a < A_; a++) acc = fmaf(as[a], W[a * D_ + d], acc);
        g_mu[k * D_ + d] = acc;
        g_muT[(size_t)d * K_ + k] = acc;
        g_muhi[k * D_ + d] = __float2bfloat16(acc);
        sq = fmaf(acc, acc, sq);
    }
    __shared__ float red[4];
#pragma unroll
    for (int off = 16; off; off >>= 1) sq += __shfl_xor_sync(0xffffffffu, sq, off);
    if ((t & 31) == 0) red[t >> 5] = sq;
    __syncthreads();
    if (t == 0) g_musq[k] = red[0] + red[1] + red[2] + red[3];
}

// ---------------- K2: theta @ mu^T + fused row softmax -> g_S ----------------
__global__ void __launch_bounds__(256)
logits_softmax_kernel(const float* __restrict__ X) {
    __shared__ float2 As2[64][37];
    __shared__ float  Bs[32][128];
    __shared__ float  musq_s[K_];

    const int rowbase = blockIdx.x * 64;
    const int tid = threadIdx.x;
    const int tx = tid & 15;
    const int ty = tid >> 4;
    if (tid < K_) musq_s[tid] = g_musq[tid];

    unsigned long long acc[4][4];
#pragma unroll
    for (int i = 0; i < 4; i++)
#pragma unroll
        for (int j = 0; j < 4; j++) acc[i][j] = 0ull;

    for (int d0 = 0; d0 < D_; d0 += 32) {
#pragma unroll
        for (int it = 0; it < 2; it++) {
            int idx = tid + it * 256;
            int r = idx >> 3;
            int c4 = (idx & 7) << 2;
            float4 va = *(const float4*)(X + (size_t)(rowbase + r) * D_ + d0 + c4);
            As2[r][c4 + 0] = make_float2(va.x, va.x);
            As2[r][c4 + 1] = make_float2(va.y, va.y);
            As2[r][c4 + 2] = make_float2(va.z, va.z);
            As2[r][c4 + 3] = make_float2(va.w, va.w);
        }
#pragma unroll
        for (int it = 0; it < 4; it++) {
            int idx = tid + it * 256;
            int kk = idx >> 5;
            int n4 = (idx & 31) << 2;
            *(float4*)&Bs[kk][n4] = *(const float4*)(g_muT + (size_t)(d0 + kk) * K_ + n4);
        }
        __syncthreads();
#pragma unroll 8
        for (int kk = 0; kk < 32; kk++) {
            ulonglong2 b01 = *(const ulonglong2*)&Bs[kk][tx * 8];
            ulonglong2 b23 = *(const ulonglong2*)&Bs[kk][tx * 8 + 4];
#pragma unroll
            for (int i = 0; i < 4; i++) {
                unsigned long long aa = *(const unsigned long long*)&As2[ty * 4 + i][kk];
                acc[i][0] = ffma2(aa, b01.x, acc[i][0]);
                acc[i][1] = ffma2(aa, b01.y, acc[i][1]);
                acc[i][2] = ffma2(aa, b23.x, acc[i][2]);
                acc[i][3] = ffma2(aa, b23.y, acc[i][3]);
            }
        }
        __syncthreads();
    }

    // Fused softmax: each row's 128 logits live in the 16-lane tx group.
#pragma unroll
    for (int i = 0; i < 4; i++) {
        int row = rowbase + ty * 4 + i;
        float l[8];
#pragma unroll
        for (int j = 0; j < 4; j++) unpack2(acc[i][j], l[2 * j], l[2 * j + 1]);
#pragma unroll
        for (int j = 0; j < 8; j++) l[j] -= 0.5f * musq_s[tx * 8 + j];
        float m = l[0];
#pragma unroll
        for (int j = 1; j < 8; j++) m = fmaxf(m, l[j]);
#pragma unroll
        for (int off = 8; off; off >>= 1) m = fmaxf(m, __shfl_xor_sync(0xffffffffu, m, off));
        float e[8], s = 0.f;
#pragma unroll
        for (int j = 0; j < 8; j++) { e[j] = expf(l[j] - m); s += e[j]; }
#pragma unroll
        for (int off = 8; off; off >>= 1) s += __shfl_xor_sync(0xffffffffu, s, off);
        float inv = 1.0f / s;
        float4 w0 = make_float4(e[0] * inv, e[1] * inv, e[2] * inv, e[3] * inv);
        float4 w1 = make_float4(e[4] * inv, e[5] * inv, e[6] * inv, e[7] * inv);
        *(float4*)&g_S[(size_t)row * K_ + tx * 8 + 0] = w0;
        *(float4*)&g_S[(size_t)row * K_ + tx * 8 + 4] = w1;
    }
}

// ---------------- K3: probe trace via mma.sync bf16, double-buffered ---------
// One CTA: probe p, 128 rows x 128 comps, K=512 in 16 chunks of 32.
// 8 warps: wm = wid&3 (rows 32*wm), wn = wid>>2 (cols 64*wn).
// Only change vs R16: software pipeline — LDG next chunk into regs, MMA on
// current SMEM buffer (hides LDG latency), STS to other buffer, ONE sync.
static constexpr int BK = 32;                 // d per chunk (64B bf16 rows)
static constexpr int NCH = D_ / BK;           // 16
static constexpr int TILE = 128 * BK * 2;     // 8 KB per operand tile

__global__ void __launch_bounds__(256, 2)
probe_mma_kernel(const int* __restrict__ Vint) {
    __shared__ __align__(1024) char smA[2][TILE];
    __shared__ __align__(1024) char smBh[2][TILE];
    __shared__ float red1[128], red2[128];

    const int tid = threadIdx.x, wid = tid >> 5, lane = tid & 31;
    const int wm = wid & 3, wn = wid >> 2;
    const int g = lane >> 2, tig = lane & 3;
    const int p = blockIdx.y, rowbase = blockIdx.x * 128;
    const size_t vbase = (size_t)p * B_ * D_ + (size_t)rowbase * D_;

    const uint32_t aBase = smem_u32(smA);
    const uint32_t bhBase = smem_u32(smBh);

    // Precompute ldmatrix lane addresses (byte offsets before k-step shift)
    const int ami = lane >> 3;                     // 0..3
    const uint32_t aRowOff[2] = {
        (uint32_t)((wm * 32 + 0 * 16 + (ami & 1) * 8 + (lane & 7)) * 64 + (ami >> 1) * 16),
        (uint32_t)((wm * 32 + 1 * 16 + (ami & 1) * 8 + (lane & 7)) * 64 + (ami >> 1) * 16)};
    const int bmi = (lane >> 3) & 1;
    const uint32_t bRowOff0 = (uint32_t)((wn * 64 + (lane & 7)) * 64 + bmi * 16);

    float acc[2][8][4];
#pragma unroll
    for (int i = 0; i < 2; i++)
#pragma unroll
        for (int j = 0; j < 8; j++)
#pragma unroll
            for (int q = 0; q < 4; q++) acc[i][j][q] = 0.f;

    // Staging registers
    int4 R[4];
    uint4 Rb[2];

    // Prologue: LDG chunk 0 (A ints + B tile), pack+STS into buf 0
#pragma unroll
    for (int i = 0; i < 4; i++) {
        int u = tid + i * 256;
        R[i] = *(const int4*)(Vint + vbase + (size_t)(u >> 3) * D_ + ((u & 7) << 2));
    }
#pragma unroll
    for (int i = 0; i < 2; i++) {
        int u = tid + i * 256;
        int n = u >> 2, c16 = u & 3;
        Rb[i] = *(const uint4*)(g_muhi + (size_t)n * D_ + c16 * 8);
    }
#pragma unroll
    for (int i = 0; i < 2; i++) {
        int u = tid + i * 256;
        int n = u >> 2, c16 = u & 3;
        *(uint4*)(smBh[0] + sw64((uint32_t)(n * 64 + c16 * 16))) = Rb[i];
    }
#pragma unroll
    for (int i = 0; i < 4; i++) {
        int u = tid + i * 256;
        int r = u >> 3, c8 = u & 7;
        uint32_t w0 = 0xBF80BF80u ^ ((uint32_t)R[i].x << 15) ^ ((uint32_t)R[i].y << 31);
        uint32_t w1 = 0xBF80BF80u ^ ((uint32_t)R[i].z << 15) ^ ((uint32_t)R[i].w << 31);
        *(uint2*)(smA[0] + sw64((uint32_t)(r * 64 + c8 * 8))) = make_uint2(w0, w1);
    }
    __syncthreads();

    for (int ch = 0; ch < NCH; ch++) {
        const int buf = ch & 1;
        const uint32_t aBuf = aBase + buf * TILE;
        const uint32_t bBuf = bhBase + buf * TILE;
        // Issue next chunk's LDGs first — latency hidden under the MMA stage
        if (ch + 1 < NCH) {
#pragma unroll
            for (int i = 0; i < 2; i++) {
                int u = tid + i * 256;
                int n = u >> 2, c16 = u & 3;
                Rb[i] = *(const uint4*)(g_muhi + (size_t)n * D_ + (ch + 1) * BK + c16 * 8);
            }
#pragma unroll
            for (int i = 0; i < 4; i++) {
                int u = tid + i * 256;
                R[i] = *(const int4*)(Vint + vbase + (size_t)(u >> 3) * D_ +
                                      (ch + 1) * BK + ((u & 7) << 2));
            }
        }
        // MMA stage on current buffer: 2 k-steps of 16
#pragma unroll
        for (int ks = 0; ks < 2; ks++) {
            uint32_t a0[4], a1[4];
            ldsm_x4(a0[0], a0[1], a0[2], a0[3], aBuf + sw64(aRowOff[0] + ks * 32));
            ldsm_x4(a1[0], a1[1], a1[2], a1[3], aBuf + sw64(aRowOff[1] + ks * 32));
#pragma unroll
            for (int nf = 0; nf < 8; nf++) {
                uint32_t boff = sw64(bRowOff0 + (uint32_t)(nf * 8 * 64) + ks * 32);
                uint32_t b0, b1;
                ldsm_x2(b0, b1, bBuf + boff);
                mma_bf16(acc[0][nf], a0[0], a0[1], a0[2], a0[3], b0, b1);
                mma_bf16(acc[1][nf], a1[0], a1[1], a1[2], a1[3], b0, b1);
            }
        }
        // Fill the other buffer and sync once
        if (ch + 1 < NCH) {
            char* aN = smA[buf ^ 1];
            char* bN = smBh[buf ^ 1];
#pragma unroll
            for (int i = 0; i < 2; i++) {
                int u = tid + i * 256;
                int n = u >> 2, c16 = u & 3;
                *(uint4*)(bN + sw64((uint32_t)(n * 64 + c16 * 16))) = Rb[i];
            }
#pragma unroll
            for (int i = 0; i < 4; i++) {
                int u = tid + i * 256;
                int r = u >> 3, c8 = u & 7;
                uint32_t w0 = 0xBF80BF80u ^ ((uint32_t)R[i].x << 15) ^ ((uint32_t)R[i].y << 31);
                uint32_t w1 = 0xBF80BF80u ^ ((uint32_t)R[i].z << 15) ^ ((uint32_t)R[i].w << 31);
                *(uint2*)(aN + sw64((uint32_t)(r * 64 + c8 * 8))) = make_uint2(w0, w1);
            }
            __syncthreads();
        }
    }

    // Epilogue: per-row trace terms s1 = sum w y^2, s2 = sum w y
    float s1[2][2] = {{0.f, 0.f}, {0.f, 0.f}};
    float s2[2][2] = {{0.f, 0.f}, {0.f, 0.f}};
#pragma unroll
    for (int mf = 0; mf < 2; mf++) {
        int r0 = rowbase + wm * 32 + mf * 16 + g;
#pragma unroll
        for (int nf = 0; nf < 8; nf++) {
            int col = wn * 64 + nf * 8 + tig * 2;
            float2 w0 = __ldg((const float2*)&g_S[(size_t)r0 * K_ + col]);
            float2 w1 = __ldg((const float2*)&g_S[(size_t)(r0 + 8) * K_ + col]);
            float c0 = acc[mf][nf][0], c1 = acc[mf][nf][1];
            float c2 = acc[mf][nf][2], c3 = acc[mf][nf][3];
            s1[mf][0] = fmaf(w0.x * c0, c0, fmaf(w0.y * c1, c1, s1[mf][0]));
            s2[mf][0] = fmaf(w0.x, c0, fmaf(w0.y, c1, s2[mf][0]));
            s1[mf][1] = fmaf(w1.x * c2, c2, fmaf(w1.y * c3, c3, s1[mf][1]));
            s2[mf][1] = fmaf(w1.x, c2, fmaf(w1.y, c3, s2[mf][1]));
        }
    }
    // reduce across the 4 tig lanes
#pragma unroll
    for (int mf = 0; mf < 2; mf++)
#pragma unroll
        for (int h = 0; h < 2; h++)
#pragma unroll
            for (int off = 1; off < 4; off <<= 1) {
                s1[mf][h] += __shfl_xor_sync(0xffffffffu, s1[mf][h], off);
                s2[mf][h] += __shfl_xor_sync(0xffffffffu, s2[mf][h], off);
            }
    __syncthreads();   // all warps done with SMEM tiles + values ready
    if (wn == 1 && tig == 0) {
#pragma unroll
        for (int mf = 0; mf < 2; mf++)
#pragma unroll
            for (int h = 0; h < 2; h++) {
                int rl = wm * 32 + mf * 16 + h * 8 + g;
                red1[rl] = s1[mf][h];
                red2[rl] = s2[mf][h];
            }
    }
    __syncthreads();
    if (wn == 0 && tig == 0) {
#pragma unroll
        for (int mf = 0; mf < 2; mf++)
#pragma unroll
            for (int h = 0; h < 2; h++) {
                int rl = wm * 32 + mf * 16 + h * 8 + g;
                float t1 = s1[mf][h] + red1[rl];
                float t2 = s2[mf][h] + red2[rl];
                g_traceP[p][rowbase + rl] = t1 - t2 * t2;
            }
    }
}

// ---------------- K4: M = w @ mu, fused sum_d (m - theta)^2 (R9-proven) ------
__global__ void __launch_bounds__(256)
wm_loss_kernel(const float* __restrict__ theta) {
    __shared__ float Ws[64][36];
    __shared__ float Ms[32][68];

    const int rowbase = blockIdx.x * 64;
    const int d0 = blockIdx.y * 64;
    const int tid = threadIdx.x;
    const int tx = tid & 15;
    const int ty = tid >> 4;

    float acc[4][4];
#pragma unroll
    for (int i = 0; i < 4; i++)
#pragma unroll
        for (int j = 0; j < 4; j++) acc[i][j] = 0.f;

    for (int k0 = 0; k0 < K_; k0 += 32) {
#pragma unroll
        for (int it = 0; it < 2; it++) {
            int idx = tid + it * 256;
            int r = idx >> 3;
            int c4 = (idx & 7) << 2;
            *(float4*)&Ws[r][c4] = *(const float4*)&g_S[(size_t)(rowbase + r) * K_ + k0 + c4];
        }
#pragma unroll
        for (int it = 0; it < 2; it++) {
            int idx = tid + it * 256;
            int kk = idx >> 4;
            int c4 = (idx & 15) << 2;
            *(float4*)&Ms[kk][c4] = *(const float4*)&g_mu[(size_t)(k0 + kk) * D_ + d0 + c4];
        }
        __syncthreads();
#pragma unroll 8
        for (int kk = 0; kk < 32; kk++) {
            float a[4], bb[4];
#pragma unroll
            for (int i = 0; i < 4; i++) a[i] = Ws[ty * 4 + i][kk];
#pragma unroll
            for (int j = 0; j < 4; j++) bb[j] = Ms[kk][tx * 4 + j];
#pragma unroll
            for (int i = 0; i < 4; i++)
#pragma unroll
                for (int j = 0; j < 4; j++) acc[i][j] = fmaf(a[i], bb[j], acc[i][j]);
        }
        __syncthreads();
    }

#pragma unroll
    for (int i = 0; i < 4; i++) {
        int row = rowbase + ty * 4 + i;
        float s = 0.f;
#pragma unroll
        for (int j = 0; j < 4; j++) {
            float th = theta[(size_t)row * D_ + d0 + tx * 4 + j];
            float df = acc[i][j] - th;
            s = fmaf(df, df, s);
        }
#pragma unroll
        for (int off = 8; off; off >>= 1) s += __shfl_xor_sync(0xffffffffu, s, off);
        if (tx == 0) g_lossPart[blockIdx.y][row] = s;
    }
}

// ---------------- K5/K6: two-stage final reduction ---------------------------
__global__ void __launch_bounds__(256)
final_partial(const int* __restrict__ pN) {
    int b = blockIdx.x * 256 + threadIdx.x;
    float Nf = (float)pN[0];
    float temper = Nf / (Nf + 1.0f);
    float tr = 0.f;
#pragma unroll
    for (int p = 0; p < P_; p++) tr += g_traceP[p][b];
    float ls = 0.f;
#pragma unroll
    for (int dt = 0; dt < DT_; dt++) ls += g_lossPart[dt][b];
    double val = (double)(0.5f * temper * temper * ls
                          + temper * (tr * (1.0f / (float)P_) - (float)D_));
    __shared__ double sd[256];
    int t = threadIdx.x;
    sd[t] = val;
    __syncthreads();
    for (int s = 128; s; s >>= 1) {
        if (t < s) sd[t] += sd[t + s];
        __syncthreads();
    }
    if (t == 0) g_part[blockIdx.x] = sd[0];
}

__global__ void final_sum(float* __restrict__ out) {
    if (threadIdx.x == 0) {
        double acc = 0.0;
#pragma unroll
        for (int i = 0; i < 16; i++) acc += g_part[i];
        out[0] = (float)(acc / (double)B_);
    }
}

// ---------------- launch ------------------------------------------------------
extern "C" void kernel_launch(void* const* d_in, const int* in_sizes, int n_in,
                              void* d_out, int out_size) {
    const float* thetas = (const float*)d_in[0];  // [B, D]
    const float* alpha  = (const float*)d_in[1];  // [K, A]
    const float* W      = (const float*)d_in[2];  // [A, D]
    const int*   v_int  = (const int*)d_in[3];    // [P, B, D]
    const int*   pN     = (const int*)d_in[4];    // N_dataset
    float* out = (float*)d_out;

    mu_kernel<<<K_, 128>>>(alpha, W);
    logits_softmax_kernel<<<B_ / 64, 256>>>(thetas);              // logits + softmax
    probe_mma_kernel<<<dim3(B_ / 128, P_), 256>>>(v_int);         // HMMA traces (pipelined)
    wm_loss_kernel<<<dim3(B_ / 64, D_ / 64), 256>>>(thetas);      // ||g||^2 parts
    final_partial<<<16, 256>>>(pN);
    final_sum<<<1, 32>>>(out);
}